// round 14
// baseline (speedup 1.0000x reference)
#include <cuda_runtime.h>
#include <cuda_bf16.h>
#include <cuda_fp16.h>
#include <math.h>
#include <cstdint>

constexpr int kN = 8192;   // num_elem
constexpr int kD = 1024;   // input_size
constexpr int kH = 1024;   // hidden_size
constexpr int kG = 2048;   // num_groups

// ---------------- device scratch ----------------
__device__ float g_u[kD];
__device__ float g_cs[kD];
__device__ float g_S;
__device__ float g_t[kH];
__device__ float g_w2[kD];
__device__ float g_c;
__device__ float g_s[kN];
__device__ float g_e[kN];
__device__ __half g_ef16[kN];
__device__ float g_vcs[kH];
__device__ float g_Z[kG];
__device__ __half g_if16[(size_t)kN * kD];         // input fp16          [n][d]
__device__ __half g_wvf[(size_t)kH * kD];          // Wv fp16             [h][d]
__device__ __half g_mT[(size_t)kG * kN];           // mask^T 0/1 fp16     [g][n]
__device__ __half g_pf[(size_t)kG * kD];           // P = (mT*e)@if16     [g][d]

// ---------------- mma helpers ----------------
__device__ __forceinline__ void ldsm4(unsigned& r0, unsigned& r1, unsigned& r2, unsigned& r3,
                                      const void* p) {
    unsigned a = (unsigned)__cvta_generic_to_shared(p);
    asm volatile("ldmatrix.sync.aligned.m8n8.x4.shared.b16 {%0,%1,%2,%3}, [%4];"
                 : "=r"(r0), "=r"(r1), "=r"(r2), "=r"(r3) : "r"(a));
}
__device__ __forceinline__ void ldsm4t(unsigned& r0, unsigned& r1, unsigned& r2, unsigned& r3,
                                       const void* p) {
    unsigned a = (unsigned)__cvta_generic_to_shared(p);
    asm volatile("ldmatrix.sync.aligned.m8n8.x4.trans.shared.b16 {%0,%1,%2,%3}, [%4];"
                 : "=r"(r0), "=r"(r1), "=r"(r2), "=r"(r3) : "r"(a));
}
__device__ __forceinline__ void mma_f16(float* c, const unsigned* a, unsigned b0, unsigned b1) {
    asm volatile("mma.sync.aligned.m16n8k16.row.col.f32.f16.f16.f32 "
                 "{%0,%1,%2,%3},{%4,%5,%6,%7},{%8,%9},{%0,%1,%2,%3};"
                 : "+f"(c[0]), "+f"(c[1]), "+f"(c[2]), "+f"(c[3])
                 : "r"(a[0]), "r"(a[1]), "r"(a[2]), "r"(a[3]), "r"(b0), "r"(b1));
}
__device__ __forceinline__ unsigned hmul2u(unsigned a, __half2 e) {
    __half2 h = __hmul2(*(__half2*)&a, e);
    return *(unsigned*)&h;
}
__device__ __forceinline__ void cp_async16(uint32_t dst, const void* src) {
    asm volatile("cp.async.cg.shared.global [%0], [%1], 16;" :: "r"(dst), "l"(src) : "memory");
}
__device__ __forceinline__ void cp_commit() {
    asm volatile("cp.async.commit_group;" ::: "memory");
}
template <int Nn>
__device__ __forceinline__ void cp_wait() {
    asm volatile("cp.async.wait_group %0;" :: "n"(Nn) : "memory");
}
__device__ __forceinline__ uint32_t smem_u32(const void* p) {
    return (uint32_t)__cvta_generic_to_shared(p);
}

extern __shared__ __align__(128) char dynsmem[];

// ---------------- init ----------------
__global__ void k_init() {
    int idx = blockIdx.x * 256 + threadIdx.x;   // grid 8 -> 2048
    if (idx < kD) { g_u[idx] = 0.f; g_w2[idx] = 0.f; g_cs[idx] = 0.f; }
    if (idx < kH) g_t[idx] = 0.f;
    if (idx == 0) g_S = 0.f;
}

// ---------------- fp32 -> fp16 (Wv and input) ----------------
__global__ void k_splitf(const float4* __restrict__ src, __half* __restrict__ dst) {
    size_t i = (size_t)blockIdx.x * 256 + threadIdx.x;
    float4 x = src[i];
    __half2 a; a.x = __float2half(x.x); a.y = __float2half(x.y);
    __half2 b; b.x = __float2half(x.z); b.y = __float2half(x.w);
    *(__half2*)(dst + 4 * i)     = a;
    *(__half2*)(dst + 4 * i + 2) = b;
}

// ---------------- transpose mask -> mT (0/1 fp16); independent of e ----------------
__global__ void k_mskT(const int* __restrict__ mask) {
    __shared__ float t[32][33];
    int gb = blockIdx.x * 32, nb = blockIdx.y * 32;
    int tx = threadIdx.x, ty = threadIdx.y;     // (32,8)
    #pragma unroll
    for (int r = 0; r < 4; r++)
        t[ty + r * 8][tx] = mask[(size_t)(nb + ty + r * 8) * kG + gb + tx] ? 1.f : 0.f;
    __syncthreads();
    #pragma unroll
    for (int r = 0; r < 4; r++)
        g_mT[(size_t)(gb + ty + r * 8) * kN + nb + tx] = __float2half(t[tx][ty + r * 8]);
}

// ---------------- u = input^T @ sw ; cs = colsum(input) ; S = sum(sw) ----------------
__global__ void k_u(const float* __restrict__ inp, const float* __restrict__ sw) {
    int d  = blockIdx.x * 256 + threadIdx.x;     // grid (4, 64)
    int n0 = blockIdx.y * (kN / 64);
    float acc = 0.f, acc2 = 0.f;
    #pragma unroll 4
    for (int n = n0; n < n0 + kN / 64; n++) {
        float x = inp[(size_t)n * kD + d];
        acc += x * sw[n];
        acc2 += x;
    }
    atomicAdd(&g_u[d], acc);
    atomicAdd(&g_cs[d], acc2);
    if (blockIdx.x == 0) {
        __shared__ float red[256];
        red[threadIdx.x] = (threadIdx.x < kN / 64) ? sw[n0 + threadIdx.x] : 0.f;
        __syncthreads();
        for (int s = 128; s > 0; s >>= 1) {
            if (threadIdx.x < s) red[threadIdx.x] += red[threadIdx.x + s];
            __syncthreads();
        }
        if (threadIdx.x == 0) atomicAdd(&g_S, red[0]);
    }
}

// ---------------- t = Wk @ u + bk * S (split-K, atomic) ----------------
__global__ void k_t(const float* __restrict__ Wk, const float* __restrict__ bk) {
    int warp = threadIdx.x >> 5, lane = threadIdx.x & 31;   // grid (128, 4)
    int row = blockIdx.x * 8 + warp;
    int k0 = blockIdx.y * 256;
    const float* w = Wk + (size_t)row * kD + k0;
    float acc = 0.f;
    #pragma unroll
    for (int k = lane; k < 256; k += 32) acc += w[k] * g_u[k0 + k];
    #pragma unroll
    for (int o = 16; o; o >>= 1) acc += __shfl_xor_sync(0xffffffffu, acc, o);
    if (lane == 0) {
        if (blockIdx.y == 0) acc += bk[row] * g_S;
        atomicAdd(&g_t[row], acc);
    }
}

// ---------------- w2 = Wq^T @ t ; c = bq.t + score_b ----------------
__global__ void k_w2c(const float* __restrict__ Wq, const float* __restrict__ bq,
                      const float* __restrict__ score_b) {
    int b = blockIdx.x;                          // grid = 257
    if (b < 256) {
        int d  = (b & 3) * 256 + threadIdx.x;
        int h0 = (b >> 2) * 16;
        float acc = 0.f;
        #pragma unroll
        for (int h = h0; h < h0 + 16; h++)
            acc += Wq[(size_t)h * kD + d] * g_t[h];
        atomicAdd(&g_w2[d], acc);
    } else {
        __shared__ float red[256];
        float acc = 0.f;
        for (int h = threadIdx.x; h < kH; h += 256) acc += bq[h] * g_t[h];
        red[threadIdx.x] = acc;
        __syncthreads();
        for (int s = 128; s > 0; s >>= 1) {
            if (threadIdx.x < s) red[threadIdx.x] += red[threadIdx.x + s];
            __syncthreads();
        }
        if (threadIdx.x == 0) g_c = red[0] + score_b[0];
    }
}

// ---------------- s[n] = input[n,:].w2 + c (float4) ----------------
__global__ void k_s(const float* __restrict__ inp) {
    int warp = threadIdx.x >> 5, lane = threadIdx.x & 31;
    int row = blockIdx.x * 8 + warp;
    const float4* r = (const float4*)(inp + (size_t)row * kD);
    const float4* w = (const float4*)g_w2;
    float acc = 0.f;
    #pragma unroll
    for (int k = lane; k < kD / 4; k += 32) {
        float4 a = r[k];
        float4 b = w[k];
        acc += a.x * b.x + a.y * b.y + a.z * b.z + a.w * b.w;
    }
    #pragma unroll
    for (int o = 16; o; o >>= 1) acc += __shfl_xor_sync(0xffffffffu, acc, o);
    if (lane == 0) g_s[row] = acc + g_c;
}

// ---------------- e = exp(s - smax), plus fp16 copy ----------------
__global__ void k_e() {
    __shared__ float red[1024];
    __shared__ float smax;
    float m = -INFINITY;
    for (int i = threadIdx.x; i < kN; i += 1024) m = fmaxf(m, g_s[i]);
    red[threadIdx.x] = m;
    __syncthreads();
    for (int s = 512; s > 0; s >>= 1) {
        if (threadIdx.x < s) red[threadIdx.x] = fmaxf(red[threadIdx.x], red[threadIdx.x + s]);
        __syncthreads();
    }
    if (threadIdx.x == 0) smax = red[0];
    __syncthreads();
    float mx = smax;
    for (int i = threadIdx.x; i < kN; i += 1024) {
        float e = expf(g_s[i] - mx);
        g_e[i] = e;
        g_ef16[i] = __float2half(e);
    }
}

// ---------------- vcs[h] = Wv[h,:].cs + N*bv[h] (off critical path) ----------------
__global__ void k_vcs(const float* __restrict__ Wv, const float* __restrict__ bv) {
    int warp = threadIdx.x >> 5, lane = threadIdx.x & 31;
    int row = blockIdx.x * 8 + warp;
    const float* w = Wv + (size_t)row * kD;
    float acc = 0.f;
    #pragma unroll 8
    for (int k = lane; k < kD; k += 32) acc += w[k] * g_cs[k];
    #pragma unroll
    for (int o = 16; o; o >>= 1) acc += __shfl_xor_sync(0xffffffffu, acc, o);
    if (lane == 0) g_vcs[row] = acc + (float)kN * bv[row];
}

// ================= Stage 1: P[G,D] = (mT*e) @ if16, e fused into A fragments =================
// K-chunk 64, 3 stages, 2 CTAs/SM.
constexpr int P_STAGES = 3;
constexpr int P_AT = 128 * 72;                   // A tile: 128g x 64k (pad 72)
constexpr int P_BT = 64 * 72;                    // B tile: 64k x 64d (pad 72)
constexpr int P_STG = P_AT + P_BT;               // 13824 elems
constexpr int P_SMEM = P_STAGES * P_STG * 2;     // 82944 bytes
constexpr int P_CHUNKS = kN / 64;                // 128

__global__ __launch_bounds__(256, 2) void k_p_mma() {
    __half* sm = (__half*)dynsmem;
    const int tid = threadIdx.x, lane = tid & 31, wid = tid >> 5;
    const int wm = (wid & 3) * 32, wn = (wid >> 2) * 32;   // 4x2 warp grid
    const int d0 = blockIdx.x * 64;
    const int g0 = blockIdx.y * 128;
    const int arow = tid >> 1, acol = (tid & 1) * 32;   // A: 128 x 64
    const int brow = tid >> 2, bcol = (tid & 3) * 16;   // B: 64 x 64
    const uint32_t sbase = smem_u32(sm);

    const __half* Ag = g_mT   + (size_t)(g0 + arow) * kN + acol;
    const __half* Bp = g_if16 + (size_t)brow * kD + d0 + bcol;
    const uint32_t adst0 = sbase + (arow * 72 + acol) * 2;
    const uint32_t bdst0 = sbase + P_AT * 2 + (brow * 72 + bcol) * 2;

    auto load_chunk = [&](int chunk, int stg) {
        uint32_t ad = adst0 + stg * P_STG * 2;
        uint32_t bd = bdst0 + stg * P_STG * 2;
        int ko = chunk * 64;
        #pragma unroll
        for (int i = 0; i < 4; i++) cp_async16(ad + 16 * i, Ag + ko + 8 * i);
        size_t boff = (size_t)ko * kD;
        cp_async16(bd,      Bp + boff);
        cp_async16(bd + 16, Bp + boff + 8);
    };

    float acc[2][4][4];
    #pragma unroll
    for (int i = 0; i < 2; i++)
        #pragma unroll
        for (int j = 0; j < 4; j++)
            #pragma unroll
            for (int q = 0; q < 4; q++) acc[i][j][q] = 0.f;

    #pragma unroll
    for (int s = 0; s < P_STAGES - 1; ++s) { load_chunk(s, s); cp_commit(); }

    const int klane = (lane & 3) * 2;
    for (int i = 0; i < P_CHUNKS; ++i) {
        cp_wait<P_STAGES - 2>();
        __syncthreads();
        const int stg = i % P_STAGES;
        __half (*SA)[72] = (__half(*)[72])(sm + stg * P_STG);
        __half (*SB)[72] = (__half(*)[72])(sm + stg * P_STG + P_AT);
        #pragma unroll
        for (int kh = 0; kh < 4; kh++) {
            int kk = kh * 16;
            int nk = i * 64 + kk;
            __half2 ea = *(const __half2*)(g_ef16 + nk + klane);
            __half2 eb = *(const __half2*)(g_ef16 + nk + 8 + klane);
            unsigned a[2][4], b[2][4];
            #pragma unroll
            for (int im = 0; im < 2; im++) {
                ldsm4(a[im][0], a[im][1], a[im][2], a[im][3],
                      &SA[wm + im * 16 + (lane & 15)][kk + (lane >> 4) * 8]);
                a[im][0] = hmul2u(a[im][0], ea);
                a[im][1] = hmul2u(a[im][1], ea);
                a[im][2] = hmul2u(a[im][2], eb);
                a[im][3] = hmul2u(a[im][3], eb);
            }
            #pragma unroll
            for (int jn = 0; jn < 2; jn++)
                ldsm4t(b[jn][0], b[jn][1], b[jn][2], b[jn][3],
                       &SB[kk + (lane & 7) + ((lane >> 3) & 1) * 8]
                          [wn + jn * 16 + (lane >> 4) * 8]);
            #pragma unroll
            for (int im = 0; im < 2; im++)
                #pragma unroll
                for (int j = 0; j < 4; j++)
                    mma_f16(acc[im][j], a[im], b[j >> 1][(j & 1) * 2],
                            b[j >> 1][(j & 1) * 2 + 1]);
        }
        __syncthreads();
        int nx = i + P_STAGES - 1;
        if (nx < P_CHUNKS) load_chunk(nx, nx % P_STAGES);
        cp_commit();
    }

    // epilogue: store P as single fp16
    const int gr = lane >> 2, gc = (lane & 3) * 2;
    #pragma unroll
    for (int im = 0; im < 2; im++) {
        #pragma unroll
        for (int r = 0; r < 2; r++) {
            int g = g0 + wm + im * 16 + gr + r * 8;
            #pragma unroll
            for (int j = 0; j < 4; j++) {
                int d = d0 + wn + j * 8 + gc;
                __half2 o;
                o.x = __float2half(acc[im][j][r * 2 + 0]);
                o.y = __float2half(acc[im][j][r * 2 + 1]);
                *(__half2*)&g_pf[(size_t)g * kD + d] = o;
            }
        }
    }
}

// ================= Stage 2: out = (P @ Wvf^T)/Z + bv, 1-term fp16 =================
constexpr int O_STAGES = 3;
constexpr int O_TS = 128 * 40;
constexpr int O_STG = 2 * O_TS;                  // Pf, Wvf
constexpr int O_SMEM = O_STAGES * O_STG * 2;     // 61440
constexpr int O_CHUNKS = kD / 32;                // 32

__global__ __launch_bounds__(256, 1) void k_out_mma(const float* __restrict__ bv,
                                                    float* __restrict__ out) {
    __half* sm = (__half*)dynsmem;
    const int tid = threadIdx.x, lane = tid & 31, wid = tid >> 5;
    const int wm = (wid & 3) * 32, wn = (wid >> 2) * 64;
    const int n0 = blockIdx.x * 128;   // h tile
    const int g0 = blockIdx.y * 128;   // group tile
    const int lrow = tid >> 1, lcol = (tid & 1) * 16;
    const uint32_t sbase = smem_u32(sm);

    const __half* Pf = g_pf  + (size_t)(g0 + lrow) * kD + lcol;
    const __half* Wf = g_wvf + (size_t)(n0 + lrow) * kD + lcol;
    const uint32_t dst0 = sbase + (lrow * 40 + lcol) * 2;

    auto load_chunk = [&](int chunk, int stg) {
        uint32_t d = dst0 + stg * O_STG * 2;
        int ko = chunk * 32;
        cp_async16(d,                 Pf + ko);
        cp_async16(d + 16,            Pf + ko + 8);
        cp_async16(d + O_TS * 2,      Wf + ko);
        cp_async16(d + O_TS * 2 + 16, Wf + ko + 8);
    };

    float acc[2][8][4];
    #pragma unroll
    for (int i = 0; i < 2; i++)
        #pragma unroll
        for (int j = 0; j < 8; j++)
            #pragma unroll
            for (int q = 0; q < 4; q++) acc[i][j][q] = 0.f;

    #pragma unroll
    for (int s = 0; s < O_STAGES - 1; ++s) { load_chunk(s, s); cp_commit(); }

    for (int i = 0; i < O_CHUNKS; ++i) {
        cp_wait<O_STAGES - 2>();
        __syncthreads();
        const int stg = i % O_STAGES;
        __half (*SP)[40] = (__half(*)[40])(sm + stg * O_STG);
        __half (*SW)[40] = (__half(*)[40])(sm + stg * O_STG + O_TS);
        #pragma unroll
        for (int kh = 0; kh < 2; kh++) {
            int kk = kh * 16;
            unsigned a[2][4], b[4][4];
            #pragma unroll
            for (int im = 0; im < 2; im++)
                ldsm4(a[im][0], a[im][1], a[im][2], a[im][3],
                      &SP[wm + im * 16 + (lane & 15)][kk + (lane >> 4) * 8]);
            #pragma unroll
            for (int jn = 0; jn < 4; jn++)
                ldsm4(b[jn][0], b[jn][1], b[jn][2], b[jn][3],
                      &SW[wn + jn * 16 + (lane & 7) + ((lane >> 4) << 3)]
                         [kk + ((lane >> 3) & 1) * 8]);
            #pragma unroll
            for (int im = 0; im < 2; im++)
                #pragma unroll
                for (int j = 0; j < 8; j++)
                    mma_f16(acc[im][j], a[im], b[j >> 1][(j & 1) * 2],
                            b[j >> 1][(j & 1) * 2 + 1]);
        }
        __syncthreads();
        int nx = i + O_STAGES - 1;
        if (nx < O_CHUNKS) load_chunk(nx, nx % O_STAGES);
        cp_commit();
    }

    // epilogue: out = acc/Z + bv, or vcs/N fallback
    const int gr = lane >> 2, gc = (lane & 3) * 2;
    #pragma unroll
    for (int im = 0; im < 2; im++) {
        #pragma unroll
        for (int r = 0; r < 2; r++) {
            int g = g0 + wm + im * 16 + gr + r * 8;
            float Zv = g_Z[g];
            if (Zv > 0.f) {
                float rZ = 1.f / Zv;
                #pragma unroll
                for (int j = 0; j < 8; j++) {
                    int h = n0 + wn + j * 8 + gc;
                    float2 o;
                    o.x = acc[im][j][r * 2 + 0] * rZ + bv[h];
                    o.y = acc[im][j][r * 2 + 1] * rZ + bv[h + 1];
                    *(float2*)&out[(size_t)g * kH + h] = o;
                }
            } else {
                const float invn = 1.f / (float)kN;
                #pragma unroll
                for (int j = 0; j < 8; j++) {
                    int h = n0 + wn + j * 8 + gc;
                    float2 o;
                    o.x = g_vcs[h] * invn;
                    o.y = g_vcs[h + 1] * invn;
                    *(float2*)&out[(size_t)g * kH + h] = o;
                }
            }
        }
    }
}

// ---- attn[g,:]: fused Z reduction + weight write (one block per g) ----
__global__ __launch_bounds__(256) void k_attn2(float* __restrict__ attn) {
    __shared__ float prod[kN];      // 32 KB
    __shared__ float red[256];
    __shared__ float zsh;
    int g = blockIdx.x;
    const __half* mrow = g_mT + (size_t)g * kN;
    float part = 0.f;
    for (int n = threadIdx.x * 8; n < kN; n += 256 * 8) {
        uint4 mv = *(const uint4*)(mrow + n);
        float4 e0 = *(const float4*)(g_e + n);
        float4 e1 = *(const float4*)(g_e + n + 4);
        const __half2* mp = (const __half2*)&mv;
        float2 m0 = __half22float2(mp[0]);
        float2 m1 = __half22float2(mp[1]);
        float2 m2 = __half22float2(mp[2]);
        float2 m3 = __half22float2(mp[3]);
        float p0 = m0.x * e0.x, p1 = m0.y * e0.y, p2 = m1.x * e0.z, p3 = m1.y * e0.w;
        float p4 = m2.x * e1.x, p5 = m2.y * e1.y, p6 = m3.x * e1.z, p7 = m3.y * e1.w;
        prod[n + 0] = p0; prod[n + 1] = p1; prod[n + 2] = p2; prod[n + 3] = p3;
        prod[n + 4] = p4; prod[n + 5] = p5; prod[n + 6] = p6; prod[n + 7] = p7;
        part += p0 + p1 + p2 + p3 + p4 + p5 + p6 + p7;
    }
    red[threadIdx.x] = part;
    __syncthreads();
    for (int s = 128; s > 0; s >>= 1) {
        if (threadIdx.x < s) red[threadIdx.x] += red[threadIdx.x + s];
        __syncthreads();
    }
    if (threadIdx.x == 0) { zsh = red[0]; g_Z[g] = red[0]; }
    __syncthreads();
    float Zv = zsh;
    bool fb = !(Zv > 0.f);
    float rZ = fb ? 0.f : 1.f / Zv;
    const float invn = 1.f / (float)kN;
    float* arow = attn + (size_t)g * kN;
    for (int n = threadIdx.x * 4; n < kN; n += 256 * 4) {
        float4 o;
        if (fb) { o.x = o.y = o.z = o.w = invn; }
        else {
            o.x = prod[n + 0] * rZ; o.y = prod[n + 1] * rZ;
            o.z = prod[n + 2] * rZ; o.w = prod[n + 3] * rZ;
        }
        *(float4*)(arow + n) = o;
    }
}

// ---------------- host launcher (multi-stream graph branches) ----------------
extern "C" void kernel_launch(void* const* d_in, const int* in_sizes, int n_in,
                              void* d_out, int out_size) {
    const float* input = (const float*)d_in[0];
    const float* Wq    = (const float*)d_in[1];
    const float* bq    = (const float*)d_in[2];
    const float* Wk    = (const float*)d_in[3];
    const float* bk    = (const float*)d_in[4];
    const float* Wv    = (const float*)d_in[5];
    const float* bv    = (const float*)d_in[6];
    const float* sw    = (const float*)d_in[7];
    const float* sb    = (const float*)d_in[8];
    const int*   mask  = (const int*)d_in[9];
    float* out = (float*)d_out;

    __half *if16, *wvf;
    cudaGetSymbolAddress((void**)&if16, g_if16);
    cudaGetSymbolAddress((void**)&wvf, g_wvf);

    static cudaStream_t s1 = nullptr, s2 = nullptr;
    static cudaEvent_t evF, ev1, evV, evMT, evZ;
    if (!s1) {
        cudaStreamCreateWithFlags(&s1, cudaStreamNonBlocking);
        cudaStreamCreateWithFlags(&s2, cudaStreamNonBlocking);
        cudaEventCreateWithFlags(&evF, cudaEventDisableTiming);
        cudaEventCreateWithFlags(&ev1, cudaEventDisableTiming);
        cudaEventCreateWithFlags(&evV, cudaEventDisableTiming);
        cudaEventCreateWithFlags(&evMT, cudaEventDisableTiming);
        cudaEventCreateWithFlags(&evZ, cudaEventDisableTiming);
        cudaFuncSetAttribute(k_p_mma, cudaFuncAttributeMaxDynamicSharedMemorySize, P_SMEM);
        cudaFuncSetAttribute(k_out_mma, cudaFuncAttributeMaxDynamicSharedMemorySize, O_SMEM);
    }

    k_init<<<8, 256>>>();
    cudaEventRecord(evF, 0);
    cudaStreamWaitEvent(s1, evF, 0);
    cudaStreamWaitEvent(s2, evF, 0);

    // s2: mask transpose — independent of e, overlaps the scalar chain
    k_mskT<<<dim3(kG / 32, kN / 32), dim3(32, 8), 0, s2>>>(mask);
    cudaEventRecord(evMT, s2);

    // s1: scalar score chain -> e (+fp16 e)  (vcs off the critical path)
    k_u<<<dim3(4, 64), 256, 0, s1>>>(input, sw);
    k_t<<<dim3(128, 4), 256, 0, s1>>>(Wk, bk);
    k_w2c<<<257, 256, 0, s1>>>(Wq, bq, sb);
    k_s<<<1024, 256, 0, s1>>>(input);
    k_e<<<1, 1024, 0, s1>>>();
    cudaEventRecord(ev1, s1);
    k_vcs<<<128, 256, 0, s1>>>(Wv, bv);
    cudaEventRecord(evV, s1);

    // s2 (cont.): fused Z + attention weights (needs mT + e), overlaps k_p_mma
    cudaStreamWaitEvent(s2, ev1, 0);
    k_attn2<<<kG, 256, 0, s2>>>(out + (size_t)kG * kH);
    cudaEventRecord(evZ, s2);

    // main: fp16 conversions during the chain, then GEMMs (e fused into p_mma)
    k_splitf<<<(kH * kD) / 1024, 256>>>((const float4*)Wv, wvf);
    k_splitf<<<(kN * kD) / 1024, 256>>>((const float4*)input, if16);
    cudaStreamWaitEvent(0, ev1, 0);                  // needs g_ef16
    cudaStreamWaitEvent(0, evMT, 0);                 // needs g_mT
    k_p_mma<<<dim3(kD / 64, kG / 128), 256, P_SMEM>>>();
    cudaStreamWaitEvent(0, evZ, 0);                  // needs g_Z
    cudaStreamWaitEvent(0, evV, 0);                  // needs g_vcs (fallback)
    k_out_mma<<<dim3(kH / 128, kG / 128), 256, O_SMEM>>>(bv, out);
}

// round 15
// speedup vs baseline: 1.0647x; 1.0647x over previous
#include <cuda_runtime.h>
#include <cuda_bf16.h>
#include <cuda_fp16.h>
#include <math.h>
#include <cstdint>

constexpr int kN = 8192;   // num_elem
constexpr int kD = 1024;   // input_size
constexpr int kH = 1024;   // hidden_size
constexpr int kG = 2048;   // num_groups

// ---------------- device scratch ----------------
__device__ float g_u[kD];
__device__ float g_cs[kD];
__device__ float g_S;
__device__ float g_t[kH];
__device__ float g_w2[kD];
__device__ float g_c;
__device__ float g_s[kN];
__device__ float g_e[kN];
__device__ __half g_ef16[kN];
__device__ float g_vcs[kH];
__device__ float g_Z[kG];
__device__ __half g_if16[(size_t)kN * kD];         // input fp16          [n][d]
__device__ __half g_wvf[(size_t)kH * kD];          // Wv fp16             [h][d]
__device__ __half g_mT[(size_t)kG * kN];           // mask^T 0/1 fp16     [g][n]
__device__ __half g_pf[(size_t)kG * kD];           // P = (mT*e)@if16     [g][d]

// ---------------- mma helpers ----------------
__device__ __forceinline__ void ldsm4(unsigned& r0, unsigned& r1, unsigned& r2, unsigned& r3,
                                      const void* p) {
    unsigned a = (unsigned)__cvta_generic_to_shared(p);
    asm volatile("ldmatrix.sync.aligned.m8n8.x4.shared.b16 {%0,%1,%2,%3}, [%4];"
                 : "=r"(r0), "=r"(r1), "=r"(r2), "=r"(r3) : "r"(a));
}
__device__ __forceinline__ void ldsm4t(unsigned& r0, unsigned& r1, unsigned& r2, unsigned& r3,
                                       const void* p) {
    unsigned a = (unsigned)__cvta_generic_to_shared(p);
    asm volatile("ldmatrix.sync.aligned.m8n8.x4.trans.shared.b16 {%0,%1,%2,%3}, [%4];"
                 : "=r"(r0), "=r"(r1), "=r"(r2), "=r"(r3) : "r"(a));
}
__device__ __forceinline__ void mma_f16(float* c, const unsigned* a, unsigned b0, unsigned b1) {
    asm volatile("mma.sync.aligned.m16n8k16.row.col.f32.f16.f16.f32 "
                 "{%0,%1,%2,%3},{%4,%5,%6,%7},{%8,%9},{%0,%1,%2,%3};"
                 : "+f"(c[0]), "+f"(c[1]), "+f"(c[2]), "+f"(c[3])
                 : "r"(a[0]), "r"(a[1]), "r"(a[2]), "r"(a[3]), "r"(b0), "r"(b1));
}
__device__ __forceinline__ unsigned hmul2u(unsigned a, __half2 e) {
    __half2 h = __hmul2(*(__half2*)&a, e);
    return *(unsigned*)&h;
}
__device__ __forceinline__ void cp_async16(uint32_t dst, const void* src) {
    asm volatile("cp.async.cg.shared.global [%0], [%1], 16;" :: "r"(dst), "l"(src) : "memory");
}
__device__ __forceinline__ void cp_commit() {
    asm volatile("cp.async.commit_group;" ::: "memory");
}
template <int Nn>
__device__ __forceinline__ void cp_wait() {
    asm volatile("cp.async.wait_group %0;" :: "n"(Nn) : "memory");
}
__device__ __forceinline__ uint32_t smem_u32(const void* p) {
    return (uint32_t)__cvta_generic_to_shared(p);
}

extern __shared__ __align__(128) char dynsmem[];

// ---------------- init ----------------
__global__ void k_init() {
    int idx = blockIdx.x * 256 + threadIdx.x;   // grid 8 -> 2048
    if (idx < kD) { g_u[idx] = 0.f; g_w2[idx] = 0.f; g_cs[idx] = 0.f; }
    if (idx < kH) g_t[idx] = 0.f;
    if (idx == 0) g_S = 0.f;
}

// ---------------- fp32 -> fp16 (Wv and input) ----------------
__global__ void k_splitf(const float4* __restrict__ src, __half* __restrict__ dst) {
    size_t i = (size_t)blockIdx.x * 256 + threadIdx.x;
    float4 x = src[i];
    __half2 a; a.x = __float2half(x.x); a.y = __float2half(x.y);
    __half2 b; b.x = __float2half(x.z); b.y = __float2half(x.w);
    *(__half2*)(dst + 4 * i)     = a;
    *(__half2*)(dst + 4 * i + 2) = b;
}

// ---------------- transpose mask -> mT (0/1 fp16); independent of e ----------------
__global__ void k_mskT(const int* __restrict__ mask) {
    __shared__ float t[32][33];
    int gb = blockIdx.x * 32, nb = blockIdx.y * 32;
    int tx = threadIdx.x, ty = threadIdx.y;     // (32,8)
    #pragma unroll
    for (int r = 0; r < 4; r++)
        t[ty + r * 8][tx] = mask[(size_t)(nb + ty + r * 8) * kG + gb + tx] ? 1.f : 0.f;
    __syncthreads();
    #pragma unroll
    for (int r = 0; r < 4; r++)
        g_mT[(size_t)(gb + ty + r * 8) * kN + nb + tx] = __float2half(t[tx][ty + r * 8]);
}

// ---------------- u = input^T @ sw ; cs = colsum(input) ; S = sum(sw) ----------------
__global__ void k_u(const float* __restrict__ inp, const float* __restrict__ sw) {
    int d  = blockIdx.x * 256 + threadIdx.x;     // grid (4, 64)
    int n0 = blockIdx.y * (kN / 64);
    float acc = 0.f, acc2 = 0.f;
    #pragma unroll 4
    for (int n = n0; n < n0 + kN / 64; n++) {
        float x = inp[(size_t)n * kD + d];
        acc += x * sw[n];
        acc2 += x;
    }
    atomicAdd(&g_u[d], acc);
    atomicAdd(&g_cs[d], acc2);
    if (blockIdx.x == 0) {
        __shared__ float red[256];
        red[threadIdx.x] = (threadIdx.x < kN / 64) ? sw[n0 + threadIdx.x] : 0.f;
        __syncthreads();
        for (int s = 128; s > 0; s >>= 1) {
            if (threadIdx.x < s) red[threadIdx.x] += red[threadIdx.x + s];
            __syncthreads();
        }
        if (threadIdx.x == 0) atomicAdd(&g_S, red[0]);
    }
}

// ---------------- t = Wk @ u + bk * S (split-K, atomic) ----------------
__global__ void k_t(const float* __restrict__ Wk, const float* __restrict__ bk) {
    int warp = threadIdx.x >> 5, lane = threadIdx.x & 31;   // grid (128, 4)
    int row = blockIdx.x * 8 + warp;
    int k0 = blockIdx.y * 256;
    const float* w = Wk + (size_t)row * kD + k0;
    float acc = 0.f;
    #pragma unroll
    for (int k = lane; k < 256; k += 32) acc += w[k] * g_u[k0 + k];
    #pragma unroll
    for (int o = 16; o; o >>= 1) acc += __shfl_xor_sync(0xffffffffu, acc, o);
    if (lane == 0) {
        if (blockIdx.y == 0) acc += bk[row] * g_S;
        atomicAdd(&g_t[row], acc);
    }
}

// ---------------- w2 = Wq^T @ t ; c = bq.t + score_b ----------------
__global__ void k_w2c(const float* __restrict__ Wq, const float* __restrict__ bq,
                      const float* __restrict__ score_b) {
    int b = blockIdx.x;                          // grid = 257
    if (b < 256) {
        int d  = (b & 3) * 256 + threadIdx.x;
        int h0 = (b >> 2) * 16;
        float acc = 0.f;
        #pragma unroll
        for (int h = h0; h < h0 + 16; h++)
            acc += Wq[(size_t)h * kD + d] * g_t[h];
        atomicAdd(&g_w2[d], acc);
    } else {
        __shared__ float red[256];
        float acc = 0.f;
        for (int h = threadIdx.x; h < kH; h += 256) acc += bq[h] * g_t[h];
        red[threadIdx.x] = acc;
        __syncthreads();
        for (int s = 128; s > 0; s >>= 1) {
            if (threadIdx.x < s) red[threadIdx.x] += red[threadIdx.x + s];
            __syncthreads();
        }
        if (threadIdx.x == 0) g_c = red[0] + score_b[0];
    }
}

// ---------------- s[n] = input[n,:].w2 + c (float4) ----------------
__global__ void k_s(const float* __restrict__ inp) {
    int warp = threadIdx.x >> 5, lane = threadIdx.x & 31;
    int row = blockIdx.x * 8 + warp;
    const float4* r = (const float4*)(inp + (size_t)row * kD);
    const float4* w = (const float4*)g_w2;
    float acc = 0.f;
    #pragma unroll
    for (int k = lane; k < kD / 4; k += 32) {
        float4 a = r[k];
        float4 b = w[k];
        acc += a.x * b.x + a.y * b.y + a.z * b.z + a.w * b.w;
    }
    #pragma unroll
    for (int o = 16; o; o >>= 1) acc += __shfl_xor_sync(0xffffffffu, acc, o);
    if (lane == 0) g_s[row] = acc + g_c;
}

// ---------------- e = exp(s - smax), plus fp16 copy ----------------
__global__ void k_e() {
    __shared__ float red[1024];
    __shared__ float smax;
    float m = -INFINITY;
    for (int i = threadIdx.x; i < kN; i += 1024) m = fmaxf(m, g_s[i]);
    red[threadIdx.x] = m;
    __syncthreads();
    for (int s = 512; s > 0; s >>= 1) {
        if (threadIdx.x < s) red[threadIdx.x] = fmaxf(red[threadIdx.x], red[threadIdx.x + s]);
        __syncthreads();
    }
    if (threadIdx.x == 0) smax = red[0];
    __syncthreads();
    float mx = smax;
    for (int i = threadIdx.x; i < kN; i += 1024) {
        float e = expf(g_s[i] - mx);
        g_e[i] = e;
        g_ef16[i] = __float2half(e);
    }
}

// ---------------- vcs[h] = Wv[h,:].cs + N*bv[h] (off critical path) ----------------
__global__ void k_vcs(const float* __restrict__ Wv, const float* __restrict__ bv) {
    int warp = threadIdx.x >> 5, lane = threadIdx.x & 31;
    int row = blockIdx.x * 8 + warp;
    const float* w = Wv + (size_t)row * kD;
    float acc = 0.f;
    #pragma unroll 8
    for (int k = lane; k < kD; k += 32) acc += w[k] * g_cs[k];
    #pragma unroll
    for (int o = 16; o; o >>= 1) acc += __shfl_xor_sync(0xffffffffu, acc, o);
    if (lane == 0) g_vcs[row] = acc + (float)kN * bv[row];
}

// ================= Stage 1: P[G,D] = (mT*e) @ if16 — R13 tiling, e fused in A regs =================
constexpr int A_STAGES = 4;
constexpr int A_ATS = 128 * 40;                  // A tile: 128g x 32k (pad 40)
constexpr int A_BTS = 32 * 72;                   // B tile: 32k x 64d (pad 72)
constexpr int A_STG_E = A_ATS + A_BTS;           // 7424 elems
constexpr int A_SMEM = A_STAGES * A_STG_E * 2;   // 59392 bytes
constexpr int A_CHUNKS = kN / 32;                // 256

__global__ __launch_bounds__(256, 2) void k_p_mma() {
    __half* sm = (__half*)dynsmem;
    const int tid = threadIdx.x, lane = tid & 31, wid = tid >> 5;
    const int wm = (wid & 3) * 32, wn = (wid >> 2) * 32;   // 4x2 warp grid
    const int d0 = blockIdx.x * 64;
    const int g0 = blockIdx.y * 128;
    const int lrow = tid >> 1, lcol = (tid & 1) * 16;   // A indices (128x32)
    const int brow = tid >> 3, bcol = (tid & 7) * 8;    // B indices (32x64)
    const uint32_t sbase = smem_u32(sm);

    const __half* Ag = g_mT   + (size_t)(g0 + lrow) * kN + lcol;
    const __half* Bp = g_if16 + (size_t)brow * kD + d0 + bcol;
    const uint32_t adst0 = sbase + (lrow * 40 + lcol) * 2;
    const uint32_t bdst0 = sbase + A_ATS * 2 + (brow * 72 + bcol) * 2;

    auto load_chunk = [&](int chunk, int stg) {
        uint32_t ad = adst0 + stg * A_STG_E * 2;
        uint32_t bd = bdst0 + stg * A_STG_E * 2;
        int ko = chunk * 32;
        cp_async16(ad,      Ag + ko);
        cp_async16(ad + 16, Ag + ko + 8);
        cp_async16(bd, Bp + (size_t)ko * kD);
    };

    float acc[2][4][4];
    #pragma unroll
    for (int i = 0; i < 2; i++)
        #pragma unroll
        for (int j = 0; j < 4; j++)
            #pragma unroll
            for (int q = 0; q < 4; q++) acc[i][j][q] = 0.f;

    #pragma unroll
    for (int s = 0; s < A_STAGES - 1; ++s) { load_chunk(s, s); cp_commit(); }

    const int klane = (lane & 3) * 2;
    for (int i = 0; i < A_CHUNKS; ++i) {
        cp_wait<A_STAGES - 2>();
        __syncthreads();
        const int stg = i % A_STAGES;
        __half (*SA)[40] = (__half(*)[40])(sm + stg * A_STG_E);
        __half (*SB)[72] = (__half(*)[72])(sm + stg * A_STG_E + A_ATS);
        #pragma unroll
        for (int kh = 0; kh < 2; kh++) {
            int kk = kh * 16;
            int nk = i * 32 + kk;
            __half2 ea = *(const __half2*)(g_ef16 + nk + klane);
            __half2 eb = *(const __half2*)(g_ef16 + nk + 8 + klane);
            unsigned a[2][4], b[2][4];
            #pragma unroll
            for (int im = 0; im < 2; im++) {
                ldsm4(a[im][0], a[im][1], a[im][2], a[im][3],
                      &SA[wm + im * 16 + (lane & 15)][kk + (lane >> 4) * 8]);
                a[im][0] = hmul2u(a[im][0], ea);
                a[im][1] = hmul2u(a[im][1], ea);
                a[im][2] = hmul2u(a[im][2], eb);
                a[im][3] = hmul2u(a[im][3], eb);
            }
            #pragma unroll
            for (int jn = 0; jn < 2; jn++)
                ldsm4t(b[jn][0], b[jn][1], b[jn][2], b[jn][3],
                       &SB[kk + (lane & 7) + ((lane >> 3) & 1) * 8]
                          [wn + jn * 16 + (lane >> 4) * 8]);
            #pragma unroll
            for (int im = 0; im < 2; im++)
                #pragma unroll
                for (int j = 0; j < 4; j++)
                    mma_f16(acc[im][j], a[im], b[j >> 1][(j & 1) * 2],
                            b[j >> 1][(j & 1) * 2 + 1]);
        }
        __syncthreads();
        int nx = i + A_STAGES - 1;
        if (nx < A_CHUNKS) load_chunk(nx, nx % A_STAGES);
        cp_commit();
    }

    // epilogue: store P as single fp16
    const int gr = lane >> 2, gc = (lane & 3) * 2;
    #pragma unroll
    for (int im = 0; im < 2; im++) {
        #pragma unroll
        for (int r = 0; r < 2; r++) {
            int g = g0 + wm + im * 16 + gr + r * 8;
            #pragma unroll
            for (int j = 0; j < 4; j++) {
                int d = d0 + wn + j * 8 + gc;
                __half2 o;
                o.x = __float2half(acc[im][j][r * 2 + 0]);
                o.y = __float2half(acc[im][j][r * 2 + 1]);
                *(__half2*)&g_pf[(size_t)g * kD + d] = o;
            }
        }
    }
}

// ================= Stage 2: out = (P @ Wvf^T)/Z + bv, 1-term fp16 =================
constexpr int O_STAGES = 3;
constexpr int O_TS = 128 * 40;
constexpr int O_STG = 2 * O_TS;                  // Pf, Wvf
constexpr int O_SMEM = O_STAGES * O_STG * 2;     // 61440
constexpr int O_CHUNKS = kD / 32;                // 32

__global__ __launch_bounds__(256, 1) void k_out_mma(const float* __restrict__ bv,
                                                    float* __restrict__ out) {
    __half* sm = (__half*)dynsmem;
    const int tid = threadIdx.x, lane = tid & 31, wid = tid >> 5;
    const int wm = (wid & 3) * 32, wn = (wid >> 2) * 64;
    const int n0 = blockIdx.x * 128;   // h tile
    const int g0 = blockIdx.y * 128;   // group tile
    const int lrow = tid >> 1, lcol = (tid & 1) * 16;
    const uint32_t sbase = smem_u32(sm);

    const __half* Pf = g_pf  + (size_t)(g0 + lrow) * kD + lcol;
    const __half* Wf = g_wvf + (size_t)(n0 + lrow) * kD + lcol;
    const uint32_t dst0 = sbase + (lrow * 40 + lcol) * 2;

    auto load_chunk = [&](int chunk, int stg) {
        uint32_t d = dst0 + stg * O_STG * 2;
        int ko = chunk * 32;
        cp_async16(d,                 Pf + ko);
        cp_async16(d + 16,            Pf + ko + 8);
        cp_async16(d + O_TS * 2,      Wf + ko);
        cp_async16(d + O_TS * 2 + 16, Wf + ko + 8);
    };

    float acc[2][8][4];
    #pragma unroll
    for (int i = 0; i < 2; i++)
        #pragma unroll
        for (int j = 0; j < 8; j++)
            #pragma unroll
            for (int q = 0; q < 4; q++) acc[i][j][q] = 0.f;

    #pragma unroll
    for (int s = 0; s < O_STAGES - 1; ++s) { load_chunk(s, s); cp_commit(); }

    for (int i = 0; i < O_CHUNKS; ++i) {
        cp_wait<O_STAGES - 2>();
        __syncthreads();
        const int stg = i % O_STAGES;
        __half (*SP)[40] = (__half(*)[40])(sm + stg * O_STG);
        __half (*SW)[40] = (__half(*)[40])(sm + stg * O_STG + O_TS);
        #pragma unroll
        for (int kh = 0; kh < 2; kh++) {
            int kk = kh * 16;
            unsigned a[2][4], b[4][4];
            #pragma unroll
            for (int im = 0; im < 2; im++)
                ldsm4(a[im][0], a[im][1], a[im][2], a[im][3],
                      &SP[wm + im * 16 + (lane & 15)][kk + (lane >> 4) * 8]);
            #pragma unroll
            for (int jn = 0; jn < 4; jn++)
                ldsm4(b[jn][0], b[jn][1], b[jn][2], b[jn][3],
                      &SW[wn + jn * 16 + (lane & 7) + ((lane >> 4) << 3)]
                         [kk + ((lane >> 3) & 1) * 8]);
            #pragma unroll
            for (int im = 0; im < 2; im++)
                #pragma unroll
                for (int j = 0; j < 8; j++)
                    mma_f16(acc[im][j], a[im], b[j >> 1][(j & 1) * 2],
                            b[j >> 1][(j & 1) * 2 + 1]);
        }
        __syncthreads();
        int nx = i + O_STAGES - 1;
        if (nx < O_CHUNKS) load_chunk(nx, nx % O_STAGES);
        cp_commit();
    }

    // epilogue: out = acc/Z + bv, or vcs/N fallback
    const int gr = lane >> 2, gc = (lane & 3) * 2;
    #pragma unroll
    for (int im = 0; im < 2; im++) {
        #pragma unroll
        for (int r = 0; r < 2; r++) {
            int g = g0 + wm + im * 16 + gr + r * 8;
            float Zv = g_Z[g];
            if (Zv > 0.f) {
                float rZ = 1.f / Zv;
                #pragma unroll
                for (int j = 0; j < 8; j++) {
                    int h = n0 + wn + j * 8 + gc;
                    float2 o;
                    o.x = acc[im][j][r * 2 + 0] * rZ + bv[h];
                    o.y = acc[im][j][r * 2 + 1] * rZ + bv[h + 1];
                    *(float2*)&out[(size_t)g * kH + h] = o;
                }
            } else {
                const float invn = 1.f / (float)kN;
                #pragma unroll
                for (int j = 0; j < 8; j++) {
                    int h = n0 + wn + j * 8 + gc;
                    float2 o;
                    o.x = g_vcs[h] * invn;
                    o.y = g_vcs[h + 1] * invn;
                    *(float2*)&out[(size_t)g * kH + h] = o;
                }
            }
        }
    }
}

// ---- attn[g,:]: fused Z reduction + weight write (one block per g) ----
__global__ __launch_bounds__(256) void k_attn2(float* __restrict__ attn) {
    __shared__ float prod[kN];      // 32 KB
    __shared__ float red[256];
    __shared__ float zsh;
    int g = blockIdx.x;
    const __half* mrow = g_mT + (size_t)g * kN;
    float part = 0.f;
    for (int n = threadIdx.x * 8; n < kN; n += 256 * 8) {
        uint4 mv = *(const uint4*)(mrow + n);
        float4 e0 = *(const float4*)(g_e + n);
        float4 e1 = *(const float4*)(g_e + n + 4);
        const __half2* mp = (const __half2*)&mv;
        float2 m0 = __half22float2(mp[0]);
        float2 m1 = __half22float2(mp[1]);
        float2 m2 = __half22float2(mp[2]);
        float2 m3 = __half22float2(mp[3]);
        float p0 = m0.x * e0.x, p1 = m0.y * e0.y, p2 = m1.x * e0.z, p3 = m1.y * e0.w;
        float p4 = m2.x * e1.x, p5 = m2.y * e1.y, p6 = m3.x * e1.z, p7 = m3.y * e1.w;
        prod[n + 0] = p0; prod[n + 1] = p1; prod[n + 2] = p2; prod[n + 3] = p3;
        prod[n + 4] = p4; prod[n + 5] = p5; prod[n + 6] = p6; prod[n + 7] = p7;
        part += p0 + p1 + p2 + p3 + p4 + p5 + p6 + p7;
    }
    red[threadIdx.x] = part;
    __syncthreads();
    for (int s = 128; s > 0; s >>= 1) {
        if (threadIdx.x < s) red[threadIdx.x] += red[threadIdx.x + s];
        __syncthreads();
    }
    if (threadIdx.x == 0) { zsh = red[0]; g_Z[g] = red[0]; }
    __syncthreads();
    float Zv = zsh;
    bool fb = !(Zv > 0.f);
    float rZ = fb ? 0.f : 1.f / Zv;
    const float invn = 1.f / (float)kN;
    float* arow = attn + (size_t)g * kN;
    for (int n = threadIdx.x * 4; n < kN; n += 256 * 4) {
        float4 o;
        if (fb) { o.x = o.y = o.z = o.w = invn; }
        else {
            o.x = prod[n + 0] * rZ; o.y = prod[n + 1] * rZ;
            o.z = prod[n + 2] * rZ; o.w = prod[n + 3] * rZ;
        }
        *(float4*)(arow + n) = o;
    }
}

// ---------------- host launcher (multi-stream graph branches) ----------------
extern "C" void kernel_launch(void* const* d_in, const int* in_sizes, int n_in,
                              void* d_out, int out_size) {
    const float* input = (const float*)d_in[0];
    const float* Wq    = (const float*)d_in[1];
    const float* bq    = (const float*)d_in[2];
    const float* Wk    = (const float*)d_in[3];
    const float* bk    = (const float*)d_in[4];
    const float* Wv    = (const float*)d_in[5];
    const float* bv    = (const float*)d_in[6];
    const float* sw    = (const float*)d_in[7];
    const float* sb    = (const float*)d_in[8];
    const int*   mask  = (const int*)d_in[9];
    float* out = (float*)d_out;

    __half *if16, *wvf;
    cudaGetSymbolAddress((void**)&if16, g_if16);
    cudaGetSymbolAddress((void**)&wvf, g_wvf);

    static cudaStream_t s1 = nullptr, s2 = nullptr;
    static cudaEvent_t evF, ev1, evV, evMT, evZ;
    if (!s1) {
        cudaStreamCreateWithFlags(&s1, cudaStreamNonBlocking);
        cudaStreamCreateWithFlags(&s2, cudaStreamNonBlocking);
        cudaEventCreateWithFlags(&evF, cudaEventDisableTiming);
        cudaEventCreateWithFlags(&ev1, cudaEventDisableTiming);
        cudaEventCreateWithFlags(&evV, cudaEventDisableTiming);
        cudaEventCreateWithFlags(&evMT, cudaEventDisableTiming);
        cudaEventCreateWithFlags(&evZ, cudaEventDisableTiming);
        cudaFuncSetAttribute(k_p_mma, cudaFuncAttributeMaxDynamicSharedMemorySize, A_SMEM);
        cudaFuncSetAttribute(k_out_mma, cudaFuncAttributeMaxDynamicSharedMemorySize, O_SMEM);
    }

    k_init<<<8, 256>>>();
    cudaEventRecord(evF, 0);
    cudaStreamWaitEvent(s1, evF, 0);
    cudaStreamWaitEvent(s2, evF, 0);

    // s2: mask transpose — independent of e, overlaps the scalar chain
    k_mskT<<<dim3(kG / 32, kN / 32), dim3(32, 8), 0, s2>>>(mask);
    cudaEventRecord(evMT, s2);

    // s1: scalar score chain -> e (+fp16 e)  (vcs off the critical path)
    k_u<<<dim3(4, 64), 256, 0, s1>>>(input, sw);
    k_t<<<dim3(128, 4), 256, 0, s1>>>(Wk, bk);
    k_w2c<<<257, 256, 0, s1>>>(Wq, bq, sb);
    k_s<<<1024, 256, 0, s1>>>(input);
    k_e<<<1, 1024, 0, s1>>>();
    cudaEventRecord(ev1, s1);
    k_vcs<<<128, 256, 0, s1>>>(Wv, bv);
    cudaEventRecord(evV, s1);

    // s2 (cont.): fused Z + attention weights (needs mT + e), overlaps k_p_mma
    cudaStreamWaitEvent(s2, ev1, 0);
    k_attn2<<<kG, 256, 0, s2>>>(out + (size_t)kG * kH);
    cudaEventRecord(evZ, s2);

    // main: fp16 conversions during the chain, then GEMMs (e fused into p_mma)
    k_splitf<<<(kH * kD) / 1024, 256>>>((const float4*)Wv, wvf);
    k_splitf<<<(kN * kD) / 1024, 256>>>((const float4*)input, if16);
    cudaStreamWaitEvent(0, ev1, 0);                  // needs g_ef16
    cudaStreamWaitEvent(0, evMT, 0);                 // needs g_mT
    k_p_mma<<<dim3(kD / 64, kG / 128), 256, A_SMEM>>>();
    cudaStreamWaitEvent(0, evZ, 0);                  // needs g_Z
    cudaStreamWaitEvent(0, evV, 0);                  // needs g_vcs (fallback)
    k_out_mma<<<dim3(kH / 128, kG / 128), 256, O_SMEM>>>(bv, out);
}

// round 17
// speedup vs baseline: 1.1648x; 1.0941x over previous
#include <cuda_runtime.h>
#include <cuda_bf16.h>
#include <cuda_fp16.h>
#include <math.h>
#include <cstdint>

constexpr int kN = 8192;   // num_elem
constexpr int kD = 1024;   // input_size
constexpr int kH = 1024;   // hidden_size
constexpr int kG = 2048;   // num_groups

// ---------------- device scratch ----------------
__device__ float g_u[kD];
__device__ float g_cs[kD];
__device__ float g_S;
__device__ float g_t[kH];
__device__ float g_w2[kD];
__device__ float g_c;
__device__ float g_s[kN];
__device__ float g_e[kN];
__device__ float g_pmax[32];
__device__ float g_vcs[kH];
__device__ float g_Z[kG];
__device__ __half g_if16[(size_t)kN * kD];         // input fp16          [n][d]
__device__ __half g_einf[(size_t)kN * kD];         // e[n]*input fp16     [n][d]
__device__ __half g_wvf[(size_t)kH * kD];          // Wv fp16             [h][d]
__device__ __half g_mT[(size_t)kG * kN];           // mask^T 0/1 fp16     [g][n]
__device__ __half g_pf[(size_t)kG * kD];           // P = mT@einf fp16    [g][d]

// ---------------- mma helpers ----------------
__device__ __forceinline__ void ldsm4(unsigned& r0, unsigned& r1, unsigned& r2, unsigned& r3,
                                      const void* p) {
    unsigned a = (unsigned)__cvta_generic_to_shared(p);
    asm volatile("ldmatrix.sync.aligned.m8n8.x4.shared.b16 {%0,%1,%2,%3}, [%4];"
                 : "=r"(r0), "=r"(r1), "=r"(r2), "=r"(r3) : "r"(a));
}
__device__ __forceinline__ void ldsm4t(unsigned& r0, unsigned& r1, unsigned& r2, unsigned& r3,
                                       const void* p) {
    unsigned a = (unsigned)__cvta_generic_to_shared(p);
    asm volatile("ldmatrix.sync.aligned.m8n8.x4.trans.shared.b16 {%0,%1,%2,%3}, [%4];"
                 : "=r"(r0), "=r"(r1), "=r"(r2), "=r"(r3) : "r"(a));
}
__device__ __forceinline__ void mma_f16(float* c, const unsigned* a, unsigned b0, unsigned b1) {
    asm volatile("mma.sync.aligned.m16n8k16.row.col.f32.f16.f16.f32 "
                 "{%0,%1,%2,%3},{%4,%5,%6,%7},{%8,%9},{%0,%1,%2,%3};"
                 : "+f"(c[0]), "+f"(c[1]), "+f"(c[2]), "+f"(c[3])
                 : "r"(a[0]), "r"(a[1]), "r"(a[2]), "r"(a[3]), "r"(b0), "r"(b1));
}
__device__ __forceinline__ void cp_async16(uint32_t dst, const void* src) {
    asm volatile("cp.async.cg.shared.global [%0], [%1], 16;" :: "r"(dst), "l"(src) : "memory");
}
__device__ __forceinline__ void cp_commit() {
    asm volatile("cp.async.commit_group;" ::: "memory");
}
template <int Nn>
__device__ __forceinline__ void cp_wait() {
    asm volatile("cp.async.wait_group %0;" :: "n"(Nn) : "memory");
}
__device__ __forceinline__ uint32_t smem_u32(const void* p) {
    return (uint32_t)__cvta_generic_to_shared(p);
}

extern __shared__ __align__(128) char dynsmem[];

// ---------------- init ----------------
__global__ void k_init() {
    int idx = blockIdx.x * 256 + threadIdx.x;   // grid 8 -> 2048
    if (idx < kD) { g_u[idx] = 0.f; g_w2[idx] = 0.f; g_cs[idx] = 0.f; }
    if (idx < kH) g_t[idx] = 0.f;
    if (idx == 0) g_S = 0.f;
}

// ---------------- fp32 -> fp16 (Wv and input) ----------------
__global__ void k_splitf(const float4* __restrict__ src, __half* __restrict__ dst) {
    size_t i = (size_t)blockIdx.x * 256 + threadIdx.x;
    float4 x = src[i];
    __half2 a; a.x = __float2half(x.x); a.y = __float2half(x.y);
    __half2 b; b.x = __float2half(x.z); b.y = __float2half(x.w);
    *(__half2*)(dst + 4 * i)     = a;
    *(__half2*)(dst + 4 * i + 2) = b;
}

// ---------------- transpose mask -> mT (0/1 fp16); independent of e ----------------
__global__ void k_mskT(const int* __restrict__ mask) {
    __shared__ float t[32][33];
    int gb = blockIdx.x * 32, nb = blockIdx.y * 32;
    int tx = threadIdx.x, ty = threadIdx.y;     // (32,8)
    #pragma unroll
    for (int r = 0; r < 4; r++)
        t[ty + r * 8][tx] = mask[(size_t)(nb + ty + r * 8) * kG + gb + tx] ? 1.f : 0.f;
    __syncthreads();
    #pragma unroll
    for (int r = 0; r < 4; r++)
        g_mT[(size_t)(gb + ty + r * 8) * kN + nb + tx] = __float2half(t[tx][ty + r * 8]);
}

// ---------------- u = input^T @ sw ; cs = colsum(input) ; S = sum(sw) ----------------
__global__ void k_u(const float* __restrict__ inp, const float* __restrict__ sw) {
    int d  = blockIdx.x * 256 + threadIdx.x;     // grid (4, 64)
    int n0 = blockIdx.y * (kN / 64);
    float acc = 0.f, acc2 = 0.f;
    #pragma unroll 4
    for (int n = n0; n < n0 + kN / 64; n++) {
        float x = inp[(size_t)n * kD + d];
        acc += x * sw[n];
        acc2 += x;
    }
    atomicAdd(&g_u[d], acc);
    atomicAdd(&g_cs[d], acc2);
    if (blockIdx.x == 0) {
        __shared__ float red[256];
        red[threadIdx.x] = (threadIdx.x < kN / 64) ? sw[n0 + threadIdx.x] : 0.f;
        __syncthreads();
        for (int s = 128; s > 0; s >>= 1) {
            if (threadIdx.x < s) red[threadIdx.x] += red[threadIdx.x + s];
            __syncthreads();
        }
        if (threadIdx.x == 0) atomicAdd(&g_S, red[0]);
    }
}

// ---------------- t = Wk @ u + bk * S (split-K, atomic) ----------------
__global__ void k_t(const float* __restrict__ Wk, const float* __restrict__ bk) {
    int warp = threadIdx.x >> 5, lane = threadIdx.x & 31;   // grid (128, 4)
    int row = blockIdx.x * 8 + warp;
    int k0 = blockIdx.y * 256;
    const float* w = Wk + (size_t)row * kD + k0;
    float acc = 0.f;
    #pragma unroll
    for (int k = lane; k < 256; k += 32) acc += w[k] * g_u[k0 + k];
    #pragma unroll
    for (int o = 16; o; o >>= 1) acc += __shfl_xor_sync(0xffffffffu, acc, o);
    if (lane == 0) {
        if (blockIdx.y == 0) acc += bk[row] * g_S;
        atomicAdd(&g_t[row], acc);
    }
}

// ---------------- w2 = Wq^T @ t ; c = bq.t + score_b ----------------
__global__ void k_w2c(const float* __restrict__ Wq, const float* __restrict__ bq,
                      const float* __restrict__ score_b) {
    int b = blockIdx.x;                          // grid = 257
    if (b < 256) {
        int d  = (b & 3) * 256 + threadIdx.x;
        int h0 = (b >> 2) * 16;
        float acc = 0.f;
        #pragma unroll
        for (int h = h0; h < h0 + 16; h++)
            acc += Wq[(size_t)h * kD + d] * g_t[h];
        atomicAdd(&g_w2[d], acc);
    } else {
        __shared__ float red[256];
        float acc = 0.f;
        for (int h = threadIdx.x; h < kH; h += 256) acc += bq[h] * g_t[h];
        red[threadIdx.x] = acc;
        __syncthreads();
        for (int s = 128; s > 0; s >>= 1) {
            if (threadIdx.x < s) red[threadIdx.x] += red[threadIdx.x + s];
            __syncthreads();
        }
        if (threadIdx.x == 0) g_c = red[0] + score_b[0];
    }
}

// ---------------- s[n] = input[n,:].w2 + c (float4) ----------------
__global__ void k_s(const float* __restrict__ inp) {
    int warp = threadIdx.x >> 5, lane = threadIdx.x & 31;
    int row = blockIdx.x * 8 + warp;
    const float4* r = (const float4*)(inp + (size_t)row * kD);
    const float4* w = (const float4*)g_w2;
    float acc = 0.f;
    #pragma unroll
    for (int k = lane; k < kD / 4; k += 32) {
        float4 a = r[k];
        float4 b = w[k];
        acc += a.x * b.x + a.y * b.y + a.z * b.z + a.w * b.w;
    }
    #pragma unroll
    for (int o = 16; o; o >>= 1) acc += __shfl_xor_sync(0xffffffffu, acc, o);
    if (lane == 0) g_s[row] = acc + g_c;
}

// ---------------- partial maxima of s (32 blocks x 256) ----------------
__global__ void k_smax() {
    __shared__ float red[256];
    int i = blockIdx.x * 256 + threadIdx.x;
    red[threadIdx.x] = g_s[i];
    __syncthreads();
    for (int s = 128; s > 0; s >>= 1) {
        if (threadIdx.x < s) red[threadIdx.x] = fmaxf(red[threadIdx.x], red[threadIdx.x + s]);
        __syncthreads();
    }
    if (threadIdx.x == 0) g_pmax[blockIdx.x] = red[0];
}

// ---- fused: global smax -> e = exp(s - smax) -> einf = fp16(e * if16) ----
__global__ __launch_bounds__(256) void k_einf(const __half* __restrict__ src,
                                              __half* __restrict__ dst) {
    __shared__ float sm_smax;
    if (threadIdx.x < 32) {
        float m = g_pmax[threadIdx.x];
        #pragma unroll
        for (int o = 16; o; o >>= 1) m = fmaxf(m, __shfl_xor_sync(0xffffffffu, m, o));
        if (threadIdx.x == 0) sm_smax = m;
    }
    __syncthreads();
    float mx = sm_smax;
    size_t i = ((size_t)blockIdx.x * 256 + threadIdx.x) * 8;
    int n = (int)(i / kD);
    float ev = expf(g_s[n] - mx);
    if ((i & (kD - 1)) == 0) g_e[n] = ev;
    uint4 v = *(const uint4*)(src + i);
    __half2* hp = (__half2*)&v;
    uint4 o;
    __half2* op = (__half2*)&o;
    #pragma unroll
    for (int j = 0; j < 4; j++) {
        float2 f = __half22float2(hp[j]);
        op[j] = __floats2half2_rn(f.x * ev, f.y * ev);
    }
    *(uint4*)(dst + i) = o;
}

// ---------------- vcs[h] = Wv[h,:].cs + N*bv[h] (off critical path) ----------------
__global__ void k_vcs(const float* __restrict__ Wv, const float* __restrict__ bv) {
    int warp = threadIdx.x >> 5, lane = threadIdx.x & 31;
    int row = blockIdx.x * 8 + warp;
    const float* w = Wv + (size_t)row * kD;
    float acc = 0.f;
    #pragma unroll 8
    for (int k = lane; k < kD; k += 32) acc += w[k] * g_cs[k];
    #pragma unroll
    for (int o = 16; o; o >>= 1) acc += __shfl_xor_sync(0xffffffffu, acc, o);
    if (lane == 0) g_vcs[row] = acc + (float)kN * bv[row];
}

// ================= Stage 1: P[G,D] = mT @ einf (fp16 mma, R13 config) =================
constexpr int A_STAGES = 4;
constexpr int A_ATS = 128 * 40;                  // A tile: 128g x 32k (pad 40)
constexpr int A_BTS = 32 * 72;                   // B tile: 32k x 64d (pad 72)
constexpr int A_STG_E = A_ATS + A_BTS;           // 7424 elems
constexpr int A_SMEM = A_STAGES * A_STG_E * 2;   // 59392 bytes
constexpr int A_CHUNKS = kN / 32;                // 256

__global__ __launch_bounds__(256, 2) void k_p_mma() {
    __half* sm = (__half*)dynsmem;
    const int tid = threadIdx.x, lane = tid & 31, wid = tid >> 5;
    const int wm = (wid & 3) * 32, wn = (wid >> 2) * 32;   // 4x2 warp grid
    const int d0 = blockIdx.x * 64;
    const int g0 = blockIdx.y * 128;
    const int lrow = tid >> 1, lcol = (tid & 1) * 16;   // A indices (128x32)
    const int brow = tid >> 3, bcol = (tid & 7) * 8;    // B indices (32x64)
    const uint32_t sbase = smem_u32(sm);

    const __half* Ag = g_mT   + (size_t)(g0 + lrow) * kN + lcol;
    const __half* Bp = g_einf + (size_t)brow * kD + d0 + bcol;
    const uint32_t adst0 = sbase + (lrow * 40 + lcol) * 2;
    const uint32_t bdst0 = sbase + A_ATS * 2 + (brow * 72 + bcol) * 2;

    auto load_chunk = [&](int chunk, int stg) {
        uint32_t ad = adst0 + stg * A_STG_E * 2;
        uint32_t bd = bdst0 + stg * A_STG_E * 2;
        int ko = chunk * 32;
        cp_async16(ad,      Ag + ko);
        cp_async16(ad + 16, Ag + ko + 8);
        cp_async16(bd, Bp + (size_t)ko * kD);
    };

    float acc[2][4][4];
    #pragma unroll
    for (int i = 0; i < 2; i++)
        #pragma unroll
        for (int j = 0; j < 4; j++)
            #pragma unroll
            for (int q = 0; q < 4; q++) acc[i][j][q] = 0.f;

    #pragma unroll
    for (int s = 0; s < A_STAGES - 1; ++s) { load_chunk(s, s); cp_commit(); }

    for (int i = 0; i < A_CHUNKS; ++i) {
        cp_wait<A_STAGES - 2>();
        __syncthreads();
        const int stg = i % A_STAGES;
        __half (*SA)[40] = (__half(*)[40])(sm + stg * A_STG_E);
        __half (*SB)[72] = (__half(*)[72])(sm + stg * A_STG_E + A_ATS);
        #pragma unroll
        for (int kh = 0; kh < 2; kh++) {
            int kk = kh * 16;
            unsigned a[2][4], b[2][4];
            #pragma unroll
            for (int im = 0; im < 2; im++)
                ldsm4(a[im][0], a[im][1], a[im][2], a[im][3],
                      &SA[wm + im * 16 + (lane & 15)][kk + (lane >> 4) * 8]);
            #pragma unroll
            for (int jn = 0; jn < 2; jn++)
                ldsm4t(b[jn][0], b[jn][1], b[jn][2], b[jn][3],
                       &SB[kk + (lane & 7) + ((lane >> 3) & 1) * 8]
                          [wn + jn * 16 + (lane >> 4) * 8]);
            #pragma unroll
            for (int im = 0; im < 2; im++)
                #pragma unroll
                for (int j = 0; j < 4; j++)
                    mma_f16(acc[im][j], a[im], b[j >> 1][(j & 1) * 2],
                            b[j >> 1][(j & 1) * 2 + 1]);
        }
        __syncthreads();
        int nx = i + A_STAGES - 1;
        if (nx < A_CHUNKS) load_chunk(nx, nx % A_STAGES);
        cp_commit();
    }

    // epilogue: store P as single fp16
    const int gr = lane >> 2, gc = (lane & 3) * 2;
    #pragma unroll
    for (int im = 0; im < 2; im++) {
        #pragma unroll
        for (int r = 0; r < 2; r++) {
            int g = g0 + wm + im * 16 + gr + r * 8;
            #pragma unroll
            for (int j = 0; j < 4; j++) {
                int d = d0 + wn + j * 8 + gc;
                __half2 o;
                o.x = __float2half(acc[im][j][r * 2 + 0]);
                o.y = __float2half(acc[im][j][r * 2 + 1]);
                *(__half2*)&g_pf[(size_t)g * kD + d] = o;
            }
        }
    }
}

// ================= Stage 2: out = (P @ Wvf^T)/Z + bv, 1-term fp16 =================
constexpr int O_STAGES = 3;
constexpr int O_TS = 128 * 40;
constexpr int O_STG = 2 * O_TS;                  // Pf, Wvf
constexpr int O_SMEM = O_STAGES * O_STG * 2;     // 61440
constexpr int O_CHUNKS = kD / 32;                // 32

__global__ __launch_bounds__(256, 1) void k_out_mma(const float* __restrict__ bv,
                                                    float* __restrict__ out) {
    __half* sm = (__half*)dynsmem;
    const int tid = threadIdx.x, lane = tid & 31, wid = tid >> 5;
    const int wm = (wid & 3) * 32, wn = (wid >> 2) * 64;
    const int n0 = blockIdx.x * 128;   // h tile
    const int g0 = blockIdx.y * 128;   // group tile
    const int lrow = tid >> 1, lcol = (tid & 1) * 16;
    const uint32_t sbase = smem_u32(sm);

    const __half* Pf = g_pf  + (size_t)(g0 + lrow) * kD + lcol;
    const __half* Wf = g_wvf + (size_t)(n0 + lrow) * kD + lcol;
    const uint32_t dst0 = sbase + (lrow * 40 + lcol) * 2;

    auto load_chunk = [&](int chunk, int stg) {
        uint32_t d = dst0 + stg * O_STG * 2;
        int ko = chunk * 32;
        cp_async16(d,                 Pf + ko);
        cp_async16(d + 16,            Pf + ko + 8);
        cp_async16(d + O_TS * 2,      Wf + ko);
        cp_async16(d + O_TS * 2 + 16, Wf + ko + 8);
    };

    float acc[2][8][4];
    #pragma unroll
    for (int i = 0; i < 2; i++)
        #pragma unroll
        for (int j = 0; j < 8; j++)
            #pragma unroll
            for (int q = 0; q < 4; q++) acc[i][j][q] = 0.f;

    #pragma unroll
    for (int s = 0; s < O_STAGES - 1; ++s) { load_chunk(s, s); cp_commit(); }

    for (int i = 0; i < O_CHUNKS; ++i) {
        cp_wait<O_STAGES - 2>();
        __syncthreads();
        const int stg = i % O_STAGES;
        __half (*SP)[40] = (__half(*)[40])(sm + stg * O_STG);
        __half (*SW)[40] = (__half(*)[40])(sm + stg * O_STG + O_TS);
        #pragma unroll
        for (int kh = 0; kh < 2; kh++) {
            int kk = kh * 16;
            unsigned a[2][4], b[4][4];
            #pragma unroll
            for (int im = 0; im < 2; im++)
                ldsm4(a[im][0], a[im][1], a[im][2], a[im][3],
                      &SP[wm + im * 16 + (lane & 15)][kk + (lane >> 4) * 8]);
            #pragma unroll
            for (int jn = 0; jn < 4; jn++)
                ldsm4(b[jn][0], b[jn][1], b[jn][2], b[jn][3],
                      &SW[wn + jn * 16 + (lane & 7) + ((lane >> 4) << 3)]
                         [kk + ((lane >> 3) & 1) * 8]);
            #pragma unroll
            for (int im = 0; im < 2; im++)
                #pragma unroll
                for (int j = 0; j < 8; j++)
                    mma_f16(acc[im][j], a[im], b[j >> 1][(j & 1) * 2],
                            b[j >> 1][(j & 1) * 2 + 1]);
        }
        __syncthreads();
        int nx = i + O_STAGES - 1;
        if (nx < O_CHUNKS) load_chunk(nx, nx % O_STAGES);
        cp_commit();
    }

    // epilogue: out = acc/Z + bv, or vcs/N fallback
    const int gr = lane >> 2, gc = (lane & 3) * 2;
    #pragma unroll
    for (int im = 0; im < 2; im++) {
        #pragma unroll
        for (int r = 0; r < 2; r++) {
            int g = g0 + wm + im * 16 + gr + r * 8;
            float Zv = g_Z[g];
            if (Zv > 0.f) {
                float rZ = 1.f / Zv;
                #pragma unroll
                for (int j = 0; j < 8; j++) {
                    int h = n0 + wn + j * 8 + gc;
                    float2 o;
                    o.x = acc[im][j][r * 2 + 0] * rZ + bv[h];
                    o.y = acc[im][j][r * 2 + 1] * rZ + bv[h + 1];
                    *(float2*)&out[(size_t)g * kH + h] = o;
                }
            } else {
                const float invn = 1.f / (float)kN;
                #pragma unroll
                for (int j = 0; j < 8; j++) {
                    int h = n0 + wn + j * 8 + gc;
                    float2 o;
                    o.x = g_vcs[h] * invn;
                    o.y = g_vcs[h + 1] * invn;
                    *(float2*)&out[(size_t)g * kH + h] = o;
                }
            }
        }
    }
}

// ---- attn[g,:]: fused Z reduction + weight write (one block per g) ----
__global__ __launch_bounds__(256) void k_attn2(float* __restrict__ attn) {
    __shared__ float prod[kN];      // 32 KB
    __shared__ float red[256];
    __shared__ float zsh;
    int g = blockIdx.x;
    const __half* mrow = g_mT + (size_t)g * kN;
    float part = 0.f;
    for (int n = threadIdx.x * 8; n < kN; n += 256 * 8) {
        uint4 mv = *(const uint4*)(mrow + n);
        float4 e0 = *(const float4*)(g_e + n);
        float4 e1 = *(const float4*)(g_e + n + 4);
        const __half2* mp = (const __half2*)&mv;
        float2 m0 = __half22float2(mp[0]);
        float2 m1 = __half22float2(mp[1]);
        float2 m2 = __half22float2(mp[2]);
        float2 m3 = __half22float2(mp[3]);
        float p0 = m0.x * e0.x, p1 = m0.y * e0.y, p2 = m1.x * e0.z, p3 = m1.y * e0.w;
        float p4 = m2.x * e1.x, p5 = m2.y * e1.y, p6 = m3.x * e1.z, p7 = m3.y * e1.w;
        prod[n + 0] = p0; prod[n + 1] = p1; prod[n + 2] = p2; prod[n + 3] = p3;
        prod[n + 4] = p4; prod[n + 5] = p5; prod[n + 6] = p6; prod[n + 7] = p7;
        part += p0 + p1 + p2 + p3 + p4 + p5 + p6 + p7;
    }
    red[threadIdx.x] = part;
    __syncthreads();
    for (int s = 128; s > 0; s >>= 1) {
        if (threadIdx.x < s) red[threadIdx.x] += red[threadIdx.x + s];
        __syncthreads();
    }
    if (threadIdx.x == 0) { zsh = red[0]; g_Z[g] = red[0]; }
    __syncthreads();
    float Zv = zsh;
    bool fb = !(Zv > 0.f);
    float rZ = fb ? 0.f : 1.f / Zv;
    const float invn = 1.f / (float)kN;
    float* arow = attn + (size_t)g * kN;
    for (int n = threadIdx.x * 4; n < kN; n += 256 * 4) {
        float4 o;
        if (fb) { o.x = o.y = o.z = o.w = invn; }
        else {
            o.x = prod[n + 0] * rZ; o.y = prod[n + 1] * rZ;
            o.z = prod[n + 2] * rZ; o.w = prod[n + 3] * rZ;
        }
        *(float4*)(arow + n) = o;
    }
}

// ---------------- host launcher (multi-stream graph branches) ----------------
extern "C" void kernel_launch(void* const* d_in, const int* in_sizes, int n_in,
                              void* d_out, int out_size) {
    const float* input = (const float*)d_in[0];
    const float* Wq    = (const float*)d_in[1];
    const float* bq    = (const float*)d_in[2];
    const float* Wk    = (const float*)d_in[3];
    const float* bk    = (const float*)d_in[4];
    const float* Wv    = (const float*)d_in[5];
    const float* bv    = (const float*)d_in[6];
    const float* sw    = (const float*)d_in[7];
    const float* sb    = (const float*)d_in[8];
    const int*   mask  = (const int*)d_in[9];
    float* out = (float*)d_out;

    __half *if16, *einf, *wvf;
    cudaGetSymbolAddress((void**)&if16, g_if16);
    cudaGetSymbolAddress((void**)&einf, g_einf);
    cudaGetSymbolAddress((void**)&wvf, g_wvf);

    static cudaStream_t s1 = nullptr, s2 = nullptr;
    static cudaEvent_t evF, ev1, evE, evV, evMT, evZ;
    if (!s1) {
        cudaStreamCreateWithFlags(&s1, cudaStreamNonBlocking);
        cudaStreamCreateWithFlags(&s2, cudaStreamNonBlocking);
        cudaEventCreateWithFlags(&evF, cudaEventDisableTiming);
        cudaEventCreateWithFlags(&ev1, cudaEventDisableTiming);
        cudaEventCreateWithFlags(&evE, cudaEventDisableTiming);
        cudaEventCreateWithFlags(&evV, cudaEventDisableTiming);
        cudaEventCreateWithFlags(&evMT, cudaEventDisableTiming);
        cudaEventCreateWithFlags(&evZ, cudaEventDisableTiming);
        cudaFuncSetAttribute(k_p_mma, cudaFuncAttributeMaxDynamicSharedMemorySize, A_SMEM);
        cudaFuncSetAttribute(k_out_mma, cudaFuncAttributeMaxDynamicSharedMemorySize, O_SMEM);
    }

    k_init<<<8, 256>>>();
    cudaEventRecord(evF, 0);
    cudaStreamWaitEvent(s1, evF, 0);
    cudaStreamWaitEvent(s2, evF, 0);

    // s2: mask transpose — independent of e, overlaps the scalar chain
    k_mskT<<<dim3(kG / 32, kN / 32), dim3(32, 8), 0, s2>>>(mask);
    cudaEventRecord(evMT, s2);

    // s1: scalar score chain -> partial maxima  (vcs off the critical path)
    k_u<<<dim3(4, 64), 256, 0, s1>>>(input, sw);
    k_t<<<dim3(128, 4), 256, 0, s1>>>(Wk, bk);
    k_w2c<<<257, 256, 0, s1>>>(Wq, bq, sb);
    k_s<<<1024, 256, 0, s1>>>(input);
    k_smax<<<32, 256, 0, s1>>>();
    cudaEventRecord(ev1, s1);
    k_vcs<<<128, 256, 0, s1>>>(Wv, bv);
    cudaEventRecord(evV, s1);

    // main: fp16 conversions during the chain, then fused e+einf, then GEMMs
    k_splitf<<<(kH * kD) / 1024, 256>>>((const float4*)Wv, wvf);
    k_splitf<<<(kN * kD) / 1024, 256>>>((const float4*)input, if16);
    cudaStreamWaitEvent(0, ev1, 0);                  // needs g_s, g_pmax
    k_einf<<<(kN * kD) / 2048, 256>>>(if16, einf);   // writes g_e + g_einf
    cudaEventRecord(evE, 0);

    // s2 (cont.): fused Z + attention weights (needs mT + e), overlaps k_p_mma
    cudaStreamWaitEvent(s2, evE, 0);
    k_attn2<<<kG, 256, 0, s2>>>(out + (size_t)kG * kH);
    cudaEventRecord(evZ, s2);

    cudaStreamWaitEvent(0, evMT, 0);                 // needs g_mT
    k_p_mma<<<dim3(kD / 64, kG / 128), 256, A_SMEM>>>();
    cudaStreamWaitEvent(0, evZ, 0);                  // needs g_Z
    cudaStreamWaitEvent(0, evV, 0);                  // needs g_vcs (fallback)
    k_out_mma<<<dim3(kH / 128, kG / 128), 256, O_SMEM>>>(bv, out);
}